// round 3
// baseline (speedup 1.0000x reference)
#include <cuda_runtime.h>
#include <math.h>

// ---------------------------------------------------------------------------
// ViT-Base forward: B=32, S=197 tokens, E=768, H=12 heads, D=64, FC=3072, L=12
// Round 1: fp32 SIMT, compute-bound 128x128x8 GEMM (8x8 microtile, float4).
// ---------------------------------------------------------------------------

#define BATCH 32
#define SEQ   197
#define EMB   768
#define HEADS 12
#define HDIM  64
#define FFN   3072
#define LAYERS 12
#define NPATCH 196
#define ROWS  (BATCH * SEQ)      // 6304
#define PROWS (BATCH * NPATCH)   // 6272

// Scratch (static device globals -- allowed; runtime allocation is not)
__device__ float g_x  [ROWS * EMB];
__device__ float g_q  [ROWS * EMB];
__device__ float g_k  [ROWS * EMB];
__device__ float g_v  [ROWS * EMB];
__device__ float g_o  [ROWS * EMB];
__device__ float g_t2 [ROWS * EMB];
__device__ float g_t1 [ROWS * FFN];   // also holds patch vectors (6272*768 fits)
__device__ float g_pos[SEQ * EMB];

// ---------------------------------------------------------------------------
// Patch extraction: img[b,c,224,224] -> patches[b*196 + (h*14+w)][(p1*16+p2)*3 + c]
// ---------------------------------------------------------------------------
__global__ void patchify_kernel(const float* __restrict__ img, float* __restrict__ out) {
    int idx = blockIdx.x * 256 + threadIdx.x;
    if (idx >= PROWS * EMB) return;
    int col = idx % EMB;
    int row = idx / EMB;
    int b = row / NPATCH, p = row % NPATCH;
    int hh = p / 14, ww = p % 14;
    int c = col % 3;
    int pp = col / 3;
    int p1 = pp / 16, p2 = pp % 16;
    out[idx] = img[((b * 3 + c) * 224 + hh * 16 + p1) * 224 + ww * 16 + p2];
}

// ---------------------------------------------------------------------------
// 2D sincos positional encoding (row 0 = zeros for cls token)
// ---------------------------------------------------------------------------
__global__ void pos_kernel(float* __restrict__ pos) {
    int idx = blockIdx.x * 256 + threadIdx.x;
    if (idx >= SEQ * EMB) return;
    int t = idx / EMB, j = idx % EMB;
    float val = 0.f;
    if (t > 0) {
        int tok = t - 1;
        int quad = j / 192;
        int i = j % 192;
        float omega = expf(-((float)i / 191.f) * logf(10000.f));
        float coord = (quad < 2) ? (float)(tok % 14) : (float)(tok / 14);
        float arg = coord * omega;
        val = (quad & 1) ? cosf(arg) : sinf(arg);
    }
    pos[idx] = val;
}

// ---------------------------------------------------------------------------
// Assemble token stream: cls + patch embeddings + positional encoding
// ---------------------------------------------------------------------------
__global__ void assemble_kernel(const float* __restrict__ emb, const float* __restrict__ cls,
                                const float* __restrict__ pos, float* __restrict__ x) {
    int idx = blockIdx.x * 256 + threadIdx.x;
    if (idx >= ROWS * EMB) return;
    int e = idx % EMB;
    int bs = idx / EMB;
    int s = bs % SEQ, b = bs / SEQ;
    float val;
    if (s == 0) val = cls[e];               // pos row 0 is zero
    else        val = emb[(b * NPATCH + s - 1) * EMB + e] + pos[s * EMB + e];
    x[idx] = val;
}

// ---------------------------------------------------------------------------
// Tiled fp32 GEMM: C[M,N] = A[M,K] @ B[K,N] (+bias) (+exact GELU)
// 128x128 tile, BK=8, 256 threads, 8x8 per-thread microtile (2x2 of 4x4).
// Requires K % 8 == 0, N % 128 == 0 (true for all calls here). M arbitrary.
// ---------------------------------------------------------------------------
#define BM 128
#define BN 128
#define BK 8
__global__ __launch_bounds__(256)
void gemm_kernel(const float* __restrict__ A, const float* __restrict__ B,
                 const float* __restrict__ bias, float* __restrict__ C,
                 int M, int N, int K, int act) {
    __shared__ float As[BK][BM];
    __shared__ float Bs[BK][BN];
    int tid = threadIdx.x;
    int bm = blockIdx.y * BM;
    int bn = blockIdx.x * BN;
    int tx = tid & 15, ty = tid >> 4;

    // global->shared load indices
    int arow = tid >> 1;          // 0..127
    int acol = (tid & 1) * 4;     // 0 or 4
    int brow = tid >> 5;          // 0..7
    int bcol = (tid & 31) * 4;    // 0..124

    float acc[8][8] = {};

    for (int k0 = 0; k0 < K; k0 += BK) {
        float4 av;
        int gr = bm + arow;
        if (gr < M) av = *(const float4*)(A + (size_t)gr * K + k0 + acol);
        else        av = make_float4(0.f, 0.f, 0.f, 0.f);
        As[acol + 0][arow] = av.x;
        As[acol + 1][arow] = av.y;
        As[acol + 2][arow] = av.z;
        As[acol + 3][arow] = av.w;

        *(float4*)(&Bs[brow][bcol]) =
            *(const float4*)(B + (size_t)(k0 + brow) * N + bn + bcol);
        __syncthreads();

        #pragma unroll
        for (int kk = 0; kk < BK; kk++) {
            float4 a0 = *(float4*)(&As[kk][ty * 4]);
            float4 a1 = *(float4*)(&As[kk][ty * 4 + 64]);
            float4 b0 = *(float4*)(&Bs[kk][tx * 4]);
            float4 b1 = *(float4*)(&Bs[kk][tx * 4 + 64]);
            float a[8] = {a0.x, a0.y, a0.z, a0.w, a1.x, a1.y, a1.z, a1.w};
            float bb[8] = {b0.x, b0.y, b0.z, b0.w, b1.x, b1.y, b1.z, b1.w};
            #pragma unroll
            for (int i = 0; i < 8; i++)
                #pragma unroll
                for (int j = 0; j < 8; j++)
                    acc[i][j] += a[i] * bb[j];
        }
        __syncthreads();
    }

    #pragma unroll
    for (int i = 0; i < 8; i++) {
        int gr = bm + ty * 4 + (i >> 2) * 64 + (i & 3);
        if (gr >= M) continue;
        #pragma unroll
        for (int j = 0; j < 8; j++) {
            int gc = bn + tx * 4 + (j >> 2) * 64 + (j & 3);
            float v = acc[i][j];
            if (bias) v += bias[gc];
            if (act == 1) v = 0.5f * v * (1.f + erff(v * 0.70710678118654752f)); // exact GELU
            C[(size_t)gr * N + gc] = v;
        }
    }
}

// ---------------------------------------------------------------------------
// Attention: one block per (s, h, b). 128 threads.
// q,k,v layout: [b, s, h*64 + d]. Writes o in same layout.
// ---------------------------------------------------------------------------
__global__ __launch_bounds__(128)
void attn_kernel(const float* __restrict__ q, const float* __restrict__ k,
                 const float* __restrict__ v, float* __restrict__ o) {
    int s = blockIdx.x, h = blockIdx.y, b = blockIdx.z;
    __shared__ float qs[HDIM];
    __shared__ float lg[SEQ];
    __shared__ float red[128];
    int tid = threadIdx.x;
    const float scale = 0.125f; // 64^-0.5

    if (tid < HDIM) qs[tid] = q[(size_t)(b * SEQ + s) * EMB + h * HDIM + tid];
    __syncthreads();

    for (int t = tid; t < SEQ; t += 128) {
        const float* kr = k + (size_t)(b * SEQ + t) * EMB + h * HDIM;
        float acc = 0.f;
        #pragma unroll
        for (int d = 0; d < HDIM; d++) acc += qs[d] * kr[d];
        lg[t] = acc * scale;
    }
    __syncthreads();

    // max
    float m = -1e30f;
    for (int t = tid; t < SEQ; t += 128) m = fmaxf(m, lg[t]);
    red[tid] = m; __syncthreads();
    for (int st = 64; st > 0; st >>= 1) {
        if (tid < st) red[tid] = fmaxf(red[tid], red[tid + st]);
        __syncthreads();
    }
    m = red[0];
    __syncthreads();

    // exp + sum
    float ssum = 0.f;
    for (int t = tid; t < SEQ; t += 128) {
        float e = expf(lg[t] - m);
        lg[t] = e;
        ssum += e;
    }
    red[tid] = ssum; __syncthreads();
    for (int st = 64; st > 0; st >>= 1) {
        if (tid < st) red[tid] += red[tid + st];
        __syncthreads();
    }
    float inv = 1.0f / red[0];
    __syncthreads();

    // o[d] = sum_t attn[t] * v[t,d]; t-range split across the two thread halves
    int d = tid & 63;
    int t0 = (tid < 64) ? 0 : 99;
    int t1 = (tid < 64) ? 99 : SEQ;
    float acc = 0.f;
    for (int t = t0; t < t1; t++)
        acc += lg[t] * v[(size_t)(b * SEQ + t) * EMB + h * HDIM + d];
    red[tid] = acc; __syncthreads();
    if (tid < 64)
        o[(size_t)(b * SEQ + s) * EMB + h * HDIM + tid] = (red[tid] + red[tid + 64]) * inv;
}

// ---------------------------------------------------------------------------
// LayerNorm over E=768, optional residual input. out may alias inp or res.
// One block (256 threads) per row.
// ---------------------------------------------------------------------------
__global__ __launch_bounds__(256)
void ln_kernel(const float* __restrict__ inp, const float* __restrict__ res,
               const float* __restrict__ g, const float* __restrict__ bb,
               float* __restrict__ out, int rows) {
    int r = blockIdx.x;
    if (r >= rows) return;
    int tid = threadIdx.x;
    const float* ip = inp + (size_t)r * EMB;
    const float* rp = res ? res + (size_t)r * EMB : nullptr;
    float v[3];
    float s = 0.f;
    #pragma unroll
    for (int i = 0; i < 3; i++) {
        int c = tid + i * 256;
        float x = ip[c];
        if (rp) x += rp[c];
        v[i] = x;
        s += x;
    }
    __shared__ float sh[256];
    sh[tid] = s; __syncthreads();
    for (int st = 128; st > 0; st >>= 1) { if (tid < st) sh[tid] += sh[tid + st]; __syncthreads(); }
    float mean = sh[0] * (1.f / EMB);
    __syncthreads();
    float s2 = 0.f;
    #pragma unroll
    for (int i = 0; i < 3; i++) { float d = v[i] - mean; s2 += d * d; }
    sh[tid] = s2; __syncthreads();
    for (int st = 128; st > 0; st >>= 1) { if (tid < st) sh[tid] += sh[tid + st]; __syncthreads(); }
    float rstd = rsqrtf(sh[0] * (1.f / EMB) + 1e-5f);
    #pragma unroll
    for (int i = 0; i < 3; i++) {
        int c = tid + i * 256;
        out[(size_t)r * EMB + c] = (v[i] - mean) * rstd * g[c] + bb[c];
    }
}

// ---------------------------------------------------------------------------
// Classifier: out[b,c] = x[b, token 0, :] @ clf_w + clf_b   (32x2)
// ---------------------------------------------------------------------------
__global__ void clf_kernel(const float* __restrict__ x, const float* __restrict__ w,
                           const float* __restrict__ b, float* __restrict__ out) {
    int idx = threadIdx.x;
    if (idx >= BATCH * 2) return;
    int bb = idx / 2, c = idx % 2;
    const float* xr = x + (size_t)bb * SEQ * EMB;  // token 0 row
    float acc = b[c];
    for (int e = 0; e < EMB; e++) acc += xr[e] * w[e * 2 + c];
    out[idx] = acc;
}

// ---------------------------------------------------------------------------
// Host orchestration
// ---------------------------------------------------------------------------
static inline void run_gemm(const float* A, const float* B, const float* bias,
                            float* C, int M, int N, int K, int act) {
    dim3 grid((N + BN - 1) / BN, (M + BM - 1) / BM);
    gemm_kernel<<<grid, 256>>>(A, B, bias, C, M, N, K, act);
}

extern "C" void kernel_launch(void* const* d_in, const int* in_sizes, int n_in,
                              void* d_out, int out_size) {
    const float* img     = (const float*)d_in[0];
    const float* patch_w = (const float*)d_in[1];
    const float* patch_b = (const float*)d_in[2];
    const float* cls_tok = (const float*)d_in[3];
    const float* Wq      = (const float*)d_in[4];
    const float* Wk      = (const float*)d_in[5];
    const float* Wv      = (const float*)d_in[6];
    const float* Wo      = (const float*)d_in[7];
    const float* bo      = (const float*)d_in[8];
    const float* ln1_g   = (const float*)d_in[9];
    const float* ln1_b   = (const float*)d_in[10];
    const float* fln_g   = (const float*)d_in[11];
    const float* fln_b   = (const float*)d_in[12];
    const float* fc1_w   = (const float*)d_in[13];
    const float* fc1_b   = (const float*)d_in[14];
    const float* fc2_w   = (const float*)d_in[15];
    const float* fc2_b   = (const float*)d_in[16];
    const float* ln2_g   = (const float*)d_in[17];
    const float* ln2_b   = (const float*)d_in[18];
    const float* clf_w   = (const float*)d_in[19];
    const float* clf_b   = (const float*)d_in[20];
    float* out = (float*)d_out;

    float *x, *q, *k, *v, *o, *t1, *t2, *pos;
    cudaGetSymbolAddress((void**)&x,   g_x);
    cudaGetSymbolAddress((void**)&q,   g_q);
    cudaGetSymbolAddress((void**)&k,   g_k);
    cudaGetSymbolAddress((void**)&v,   g_v);
    cudaGetSymbolAddress((void**)&o,   g_o);
    cudaGetSymbolAddress((void**)&t1,  g_t1);
    cudaGetSymbolAddress((void**)&t2,  g_t2);
    cudaGetSymbolAddress((void**)&pos, g_pos);

    // --- Embedding ---
    patchify_kernel<<<(PROWS * EMB + 255) / 256, 256>>>(img, t1);
    pos_kernel<<<(SEQ * EMB + 255) / 256, 256>>>(pos);
    run_gemm(t1, patch_w, patch_b, t2, PROWS, EMB, EMB, 0);
    assemble_kernel<<<(ROWS * EMB + 255) / 256, 256>>>(t2, cls_tok, pos, x);

    // --- Transformer layers ---
    for (int l = 0; l < LAYERS; l++) {
        const float* wq = Wq + (size_t)l * EMB * EMB;
        const float* wk = Wk + (size_t)l * EMB * EMB;
        const float* wv = Wv + (size_t)l * EMB * EMB;
        const float* wo = Wo + (size_t)l * EMB * EMB;
        const float* w1 = fc1_w + (size_t)l * EMB * FFN;
        const float* w2 = fc2_w + (size_t)l * FFN * EMB;

        run_gemm(x, wq, nullptr, q, ROWS, EMB, EMB, 0);
        run_gemm(x, wk, nullptr, k, ROWS, EMB, EMB, 0);
        run_gemm(x, wv, nullptr, v, ROWS, EMB, EMB, 0);

        dim3 agrid(SEQ, HEADS, BATCH);
        attn_kernel<<<agrid, 128>>>(q, k, v, o);

        run_gemm(o, wo, bo + l * EMB, t2, ROWS, EMB, EMB, 0);
        ln_kernel<<<ROWS, 256>>>(t2, x, ln1_g + l * EMB, ln1_b + l * EMB, x, ROWS);

        ln_kernel<<<ROWS, 256>>>(x, nullptr, fln_g + l * EMB, fln_b + l * EMB, t2, ROWS);
        run_gemm(t2, w1, fc1_b + l * FFN, t1, ROWS, FFN, EMB, 1);   // + exact GELU
        run_gemm(t1, w2, fc2_b + l * EMB, t2, ROWS, EMB, FFN, 0);
        ln_kernel<<<ROWS, 256>>>(t2, x, ln2_g + l * EMB, ln2_b + l * EMB, x, ROWS);
    }

    // --- Classifier head ---
    clf_kernel<<<1, 64>>>(x, clf_w, clf_b, out);
}